// round 10
// baseline (speedup 1.0000x reference)
#include <cuda_runtime.h>
#include <cuda_fp16.h>

#define RES 2048
#define TBL_ENTRIES (RES * RES)

// 128 MB scratch: entry [y][x] = full 2x2 patch, fp16, 32B-aligned.
// half2 words: w0=(c00.0,c10.0) w1=(c00.1,c10.1) w2=(c00.2,c10.2)
//              w3=(c01.0,c11.0) w4=(c01.1,c11.1) w5=(c01.2,c11.2)  w6,w7 pad
struct __align__(32) Entry { uint4 lo; uint4 hi; };
__device__ Entry g_vp[TBL_ENTRIES];

__device__ __forceinline__ unsigned pack2(float lo, float hi)
{
    __half2 h = __floats2half2_rn(lo, hi);
    return *reinterpret_cast<unsigned*>(&h);
}

__global__ void __launch_bounds__(256) repack_kernel(const float* __restrict__ grid)
{
    int idx = blockIdx.x * blockDim.x + threadIdx.x;
    if (idx >= TBL_ENTRIES) return;

    int y  = idx >> 11;
    int x  = idx & (RES - 1);
    int x1 = min(x + 1, RES - 1);
    int y1 = min(y + 1, RES - 1);

    const float* p00 = grid + ((size_t)(y  << 11) + x ) * 3;
    const float* p01 = grid + ((size_t)(y  << 11) + x1) * 3;
    const float* p10 = grid + ((size_t)(y1 << 11) + x ) * 3;
    const float* p11 = grid + ((size_t)(y1 << 11) + x1) * 3;

    float a0 = __ldg(p00 + 0), a1 = __ldg(p00 + 1), a2 = __ldg(p00 + 2); // c00
    float b0 = __ldg(p01 + 0), b1 = __ldg(p01 + 1), b2 = __ldg(p01 + 2); // c01
    float c0 = __ldg(p10 + 0), c1 = __ldg(p10 + 1), c2 = __ldg(p10 + 2); // c10
    float d0 = __ldg(p11 + 0), d1 = __ldg(p11 + 1), d2 = __ldg(p11 + 2); // c11

    uint4 lo, hi;
    lo.x = pack2(a0, c0);
    lo.y = pack2(a1, c1);
    lo.z = pack2(a2, c2);
    lo.w = pack2(b0, d0);
    hi.x = pack2(b1, d1);
    hi.y = pack2(b2, d2);
    hi.z = 0u;
    hi.w = 0u;

    // plain coalesced 16B stores (no 256-bit store — bisecting round 8's hang)
    g_vp[idx].lo = lo;
    g_vp[idx].hi = hi;
}

__global__ void __launch_bounds__(256) bilerp_kernel(
    const float* __restrict__ pts,    // [N,2]
    float* __restrict__ out,          // [N,3]
    int n)
{
    int i = blockIdx.x * blockDim.x + threadIdx.x;
    if (i >= n) return;

    float2 p = reinterpret_cast<const float2*>(pts)[i];

    const float scale = (float)(RES - 1);
    float sx = p.x * scale;
    float sy = p.y * scale;

    int xl = min(max((int)floorf(sx), 0), RES - 2);
    int yl = min(max((int)floorf(sy), 0), RES - 2);

    float tx = sx - (float)xl;
    float ty = sy - (float)yl;
    float omtx = 1.0f - tx;
    float omty = 1.0f - ty;

    // ONE 256-bit load fetches the whole 2x2 patch (32B aligned, 1 sector, 1 line)
    unsigned w0, w1, w2, w3, w4, w5, w6, w7;
    asm volatile(
        "ld.global.nc.v8.b32 {%0,%1,%2,%3,%4,%5,%6,%7}, [%8];"
        : "=r"(w0), "=r"(w1), "=r"(w2), "=r"(w3),
          "=r"(w4), "=r"(w5), "=r"(w6), "=r"(w7)
        : "l"(&g_vp[(yl << 11) + xl])
        : "memory");

    float2 l0 = __half22float2(*reinterpret_cast<__half2*>(&w0)); // (c00.0, c10.0)
    float2 l1 = __half22float2(*reinterpret_cast<__half2*>(&w1));
    float2 l2 = __half22float2(*reinterpret_cast<__half2*>(&w2));
    float2 r0 = __half22float2(*reinterpret_cast<__half2*>(&w3)); // (c01.0, c11.0)
    float2 r1 = __half22float2(*reinterpret_cast<__half2*>(&w4));
    float2 r2 = __half22float2(*reinterpret_cast<__half2*>(&w5));
    (void)w6; (void)w7;

    float o0 = (l0.x * omtx + r0.x * tx) * omty + (l0.y * omtx + r0.y * tx) * ty;
    float o1 = (l1.x * omtx + r1.x * tx) * omty + (l1.y * omtx + r1.y * tx) * ty;
    float o2 = (l2.x * omtx + r2.x * tx) * omty + (l2.y * omtx + r2.y * tx) * ty;

    float* o = out + (size_t)i * 3;
    o[0] = o0;
    o[1] = o1;
    o[2] = o2;
}

extern "C" void kernel_launch(void* const* d_in, const int* in_sizes, int n_in,
                              void* d_out, int out_size)
{
    const float* pts  = (const float*)d_in[0];
    const float* grid = (const float*)d_in[1];

    int threads = 256;

    int rblocks = (TBL_ENTRIES + threads - 1) / threads;
    repack_kernel<<<rblocks, threads>>>(grid);

    int n = in_sizes[0] / 2;
    int blocks = (n + threads - 1) / threads;
    bilerp_kernel<<<blocks, threads>>>(pts, (float*)d_out, n);
}

// round 11
// speedup vs baseline: 1.4897x; 1.4897x over previous
#include <cuda_runtime.h>
#include <cuda_fp16.h>

#define RES 2048
#define TBL_ENTRIES (RES * RES)

// 64 MB scratch: entry [y][x] = { (f[y][x][c], f[y+1][x][c]) packed as half2, c=0..2, pad }
__device__ uint4 g_vp[TBL_ENTRIES];

__global__ void __launch_bounds__(256) repack_kernel(const float* __restrict__ grid)
{
    int idx = blockIdx.x * blockDim.x + threadIdx.x;
    if (idx >= TBL_ENTRIES) return;

    int y = idx >> 11;
    int x = idx & (RES - 1);
    int y1 = min(y + 1, RES - 1);

    const float* p0 = grid + (size_t)idx * 3;
    const float* p1 = grid + ((size_t)(y1 << 11) + x) * 3;

    float a0 = __ldg(p0 + 0), a1 = __ldg(p0 + 1), a2 = __ldg(p0 + 2);
    float b0 = __ldg(p1 + 0), b1 = __ldg(p1 + 1), b2 = __ldg(p1 + 2);

    __half2 h0 = __floats2half2_rn(a0, b0);
    __half2 h1 = __floats2half2_rn(a1, b1);
    __half2 h2 = __floats2half2_rn(a2, b2);

    uint4 v;
    v.x = *reinterpret_cast<unsigned int*>(&h0);
    v.y = *reinterpret_cast<unsigned int*>(&h1);
    v.z = *reinterpret_cast<unsigned int*>(&h2);
    v.w = 0u;
    g_vp[idx] = v;
}

__global__ void __launch_bounds__(256) bilerp_kernel(
    const float* __restrict__ pts,    // [N,2]
    float* __restrict__ out,          // [N,3]
    int n)
{
    int i = blockIdx.x * blockDim.x + threadIdx.x;
    if (i >= n) return;

    // evict-first streaming read: do not let the point stream evict the table from L2
    float2 p = __ldcs(reinterpret_cast<const float2*>(pts) + i);

    const float scale = (float)(RES - 1);
    float sx = p.x * scale;
    float sy = p.y * scale;

    int xl = min(max((int)floorf(sx), 0), RES - 2);
    int yl = min(max((int)floorf(sy), 0), RES - 2);

    float tx = sx - (float)xl;
    float ty = sy - (float)yl;
    float omtx = 1.0f - tx;
    float omty = 1.0f - ty;

    int base = (yl << 11) + xl;
    // table gathers: normal caching (L2-resident table is the whole point)
    uint4 L = __ldg(&g_vp[base]);        // (c00, c10) per channel
    uint4 R = __ldg(&g_vp[base + 1]);    // (c01, c11) per channel

    float2 l0 = __half22float2(*reinterpret_cast<__half2*>(&L.x));
    float2 l1 = __half22float2(*reinterpret_cast<__half2*>(&L.y));
    float2 l2 = __half22float2(*reinterpret_cast<__half2*>(&L.z));
    float2 r0 = __half22float2(*reinterpret_cast<__half2*>(&R.x));
    float2 r1 = __half22float2(*reinterpret_cast<__half2*>(&R.y));
    float2 r2 = __half22float2(*reinterpret_cast<__half2*>(&R.z));

    float o0 = (l0.x * omtx + r0.x * tx) * omty + (l0.y * omtx + r0.y * tx) * ty;
    float o1 = (l1.x * omtx + r1.x * tx) * omty + (l1.y * omtx + r1.y * tx) * ty;
    float o2 = (l2.x * omtx + r2.x * tx) * omty + (l2.y * omtx + r2.y * tx) * ty;

    // evict-first streaming stores: keep the table resident in L2
    float* o = out + (size_t)i * 3;
    __stcs(o + 0, o0);
    __stcs(o + 1, o1);
    __stcs(o + 2, o2);
}

extern "C" void kernel_launch(void* const* d_in, const int* in_sizes, int n_in,
                              void* d_out, int out_size)
{
    const float* pts  = (const float*)d_in[0];
    const float* grid = (const float*)d_in[1];

    int threads = 256;

    int rblocks = (TBL_ENTRIES + threads - 1) / threads;
    repack_kernel<<<rblocks, threads>>>(grid);

    int n = in_sizes[0] / 2;
    int blocks = (n + threads - 1) / threads;
    bilerp_kernel<<<blocks, threads>>>(pts, (float*)d_out, n);
}

// round 14
// speedup vs baseline: 1.5406x; 1.0342x over previous
#include <cuda_runtime.h>
#include <cuda_fp16.h>

#define RES 2048
#define TBL_ENTRIES (RES * RES)

// 64 MB scratch: entry [y][x] = { (f[y][x][c], f[y+1][x][c]) packed as half2, c=0..2, pad }
__device__ uint4 g_vp[TBL_ENTRIES];

__global__ void __launch_bounds__(256) repack_kernel(const float* __restrict__ grid)
{
    int idx = blockIdx.x * blockDim.x + threadIdx.x;
    if (idx >= TBL_ENTRIES) return;

    int y = idx >> 11;
    int x = idx & (RES - 1);
    int y1 = min(y + 1, RES - 1);

    const float* p0 = grid + (size_t)idx * 3;
    const float* p1 = grid + ((size_t)(y1 << 11) + x) * 3;

    float a0 = __ldg(p0 + 0), a1 = __ldg(p0 + 1), a2 = __ldg(p0 + 2);
    float b0 = __ldg(p1 + 0), b1 = __ldg(p1 + 1), b2 = __ldg(p1 + 2);

    __half2 h0 = __floats2half2_rn(a0, b0);
    __half2 h1 = __floats2half2_rn(a1, b1);
    __half2 h2 = __floats2half2_rn(a2, b2);

    unsigned w0 = *reinterpret_cast<unsigned*>(&h0);
    unsigned w1 = *reinterpret_cast<unsigned*>(&h1);
    unsigned w2 = *reinterpret_cast<unsigned*>(&h2);

    // sticky-L2 store via createpolicy + cache_hint (immediate evict_last only legal on 32B ops)
    unsigned long long pol;
    asm("createpolicy.fractional.L2::evict_last.b64 %0, 1.0;" : "=l"(pol));
    asm volatile(
        "st.global.L2::cache_hint.v4.b32 [%0], {%1,%2,%3,%4}, %5;"
        :: "l"(&g_vp[idx]), "r"(w0), "r"(w1), "r"(w2), "r"(0u), "l"(pol)
        : "memory");
}

__global__ void __launch_bounds__(256) bilerp_kernel(
    const float* __restrict__ pts,    // [N,2]
    float* __restrict__ out,          // [N,3]
    int n)
{
    int i = blockIdx.x * blockDim.x + threadIdx.x;
    if (i >= n) return;

    // evict-first streaming read of the point
    float2 p = __ldcs(reinterpret_cast<const float2*>(pts) + i);

    const float scale = (float)(RES - 1);
    float sx = p.x * scale;
    float sy = p.y * scale;

    int xl = min(max((int)floorf(sx), 0), RES - 2);
    int yl = min(max((int)floorf(sy), 0), RES - 2);

    float tx = sx - (float)xl;
    float ty = sy - (float)yl;
    float omtx = 1.0f - tx;
    float omty = 1.0f - ty;

    int base = (yl << 11) + xl;

    // sticky-L2 table gathers via policy register
    unsigned long long pol;
    asm("createpolicy.fractional.L2::evict_last.b64 %0, 1.0;" : "=l"(pol));

    unsigned Lx, Ly, Lz, Lw, Rx, Ry, Rz, Rw;
    asm volatile(
        "ld.global.nc.L2::cache_hint.v4.b32 {%0,%1,%2,%3}, [%4], %5;"
        : "=r"(Lx), "=r"(Ly), "=r"(Lz), "=r"(Lw)
        : "l"(&g_vp[base]), "l"(pol));
    asm volatile(
        "ld.global.nc.L2::cache_hint.v4.b32 {%0,%1,%2,%3}, [%4], %5;"
        : "=r"(Rx), "=r"(Ry), "=r"(Rz), "=r"(Rw)
        : "l"(&g_vp[base + 1]), "l"(pol));
    (void)Lw; (void)Rw;

    float2 l0 = __half22float2(*reinterpret_cast<__half2*>(&Lx)); // (c00.0, c10.0)
    float2 l1 = __half22float2(*reinterpret_cast<__half2*>(&Ly));
    float2 l2 = __half22float2(*reinterpret_cast<__half2*>(&Lz));
    float2 r0 = __half22float2(*reinterpret_cast<__half2*>(&Rx)); // (c01.0, c11.0)
    float2 r1 = __half22float2(*reinterpret_cast<__half2*>(&Ry));
    float2 r2 = __half22float2(*reinterpret_cast<__half2*>(&Rz));

    float o0 = (l0.x * omtx + r0.x * tx) * omty + (l0.y * omtx + r0.y * tx) * ty;
    float o1 = (l1.x * omtx + r1.x * tx) * omty + (l1.y * omtx + r1.y * tx) * ty;
    float o2 = (l2.x * omtx + r2.x * tx) * omty + (l2.y * omtx + r2.y * tx) * ty;

    // evict-first streaming stores
    float* o = out + (size_t)i * 3;
    __stcs(o + 0, o0);
    __stcs(o + 1, o1);
    __stcs(o + 2, o2);
}

extern "C" void kernel_launch(void* const* d_in, const int* in_sizes, int n_in,
                              void* d_out, int out_size)
{
    const float* pts  = (const float*)d_in[0];
    const float* grid = (const float*)d_in[1];

    int threads = 256;

    int rblocks = (TBL_ENTRIES + threads - 1) / threads;
    repack_kernel<<<rblocks, threads>>>(grid);

    int n = in_sizes[0] / 2;
    int blocks = (n + threads - 1) / threads;
    bilerp_kernel<<<blocks, threads>>>(pts, (float*)d_out, n);
}